// round 4
// baseline (speedup 1.0000x reference)
#include <cuda_runtime.h>

// Problem constants (fixed by the reference):
//   N_NODES = 2048, N_ELEMS = 4096
//   Output: (N + 2E) x (2E + N) = 10240 x 10240 fp32
#define NN 2048
#define EE 4096
#define WW (2 * EE + NN)   // 10240
#define W4 (WW / 4)        // 2560

// Fill: one block per output row; 256 threads x 10 float4 = 2560 float4 = row.
#define NUM_FILL_BLOCKS WW                       // 10240
// Transpose: 64x64 tiles over the E x N (-M^T) block
#define TP_TILE 64
#define TP_TILES_X (EE / TP_TILE)                // 64 (e tiles)
#define TP_TILES_Y (NN / TP_TILE)                // 32 (n tiles)
#define NUM_TP_BLOCKS (TP_TILES_X * TP_TILES_Y)  // 2048
#define TOTAL_BLOCKS (NUM_FILL_BLOCKS + NUM_TP_BLOCKS)   // 12288

__global__ void __launch_bounds__(256) fused_kernel(
    const float* __restrict__ M,
    const float* __restrict__ params,
    const int* __restrict__ kinds,
    float* __restrict__ out)
{
    const int bid = blockIdx.x;
    const int tid = threadIdx.x;

    if (bid < NUM_FILL_BLOCKS) {
        // ------------------------------------------------------------------
        // FILL path: this block owns output row `bid` (2560 float4s).
        // Thread t writes c4 = t + 256*i for i = 0..9.
        // ------------------------------------------------------------------
        const int row = bid;
        float4* orow4 = reinterpret_cast<float4*>(out) + (long)row * W4;
        const float4 zero4 = make_float4(0.f, 0.f, 0.f, 0.f);

        if (row < NN) {
            // kcl: [ M | 0 ].  col < EE  <=>  c4 < 1024  <=>  i <= 3.
            const float4* mrow4 = reinterpret_cast<const float4*>(M) + (long)row * (EE / 4);
            #pragma unroll
            for (int i = 0; i < 4; i++) {
                const int c4 = tid + 256 * i;
                __stcs(&orow4[c4], mrow4[c4]);
            }
            #pragma unroll
            for (int i = 4; i < 10; i++) {
                __stcs(&orow4[tid + 256 * i], zero4);
            }
        } else if (row < NN + EE) {
            // kvl: [ 0 | I_E | (-M^T: skipped) ].  Write cols [0, 2E) only:
            // c4 < 2048 <=> i <= 7 (tid + 256*7 = max 2047).
            const int r  = row - NN;
            const int d  = EE + r;           // identity column
            const int dc4 = d >> 2;
            const int dl  = d & 3;
            #pragma unroll
            for (int i = 0; i < 8; i++) {
                const int c4 = tid + 256 * i;
                float4 v = zero4;
                if (c4 == dc4) reinterpret_cast<float*>(&v)[dl] = 1.0f;
                __stcs(&orow4[c4], v);
            }
        } else {
            // elem: zeros + z diag at col=pos, y diag at col=E+pos.
            const int pos = row - NN - EE;
            const float p = params[pos];
            const int   k = kinds[pos];
            float z = 0.0f;
            if (k == 0)                      z = -p;   // R
            else if (k == 2)                 z = 1.0f; // VC
            else if (k == 3 && !(p > 0.0f))  z = 1.0f; // SW off
            const float y = (k == 0 || k == 1 || (k == 3 && p > 0.0f)) ? 1.0f : 0.0f;

            const int zc4 = pos >> 2;
            const int yc4 = (EE + pos) >> 2;
            const int l   = pos & 3;                 // same lane for both

            #pragma unroll
            for (int i = 0; i < 10; i++) {
                const int c4 = tid + 256 * i;
                float4 v = zero4;
                if (c4 == zc4) reinterpret_cast<float*>(&v)[l] = z;
                if (c4 == yc4) reinterpret_cast<float*>(&v)[l] = y;
                __stcs(&orow4[c4], v);
            }
        }
    } else {
        // ------------------------------------------------------------------
        // TRANSPOSE path: out[NN + e][2*EE + n] = -M[n][e], 64x64 tiles.
        // 256 threads; 4 float4 loads + 4 float4 stores per thread.
        // ------------------------------------------------------------------
        __shared__ float tile[TP_TILE][TP_TILE + 1];   // [n_local][e_local]

        const int t  = bid - NUM_FILL_BLOCKS;
        const int et = t % TP_TILES_X;
        const int nt = t / TP_TILES_X;
        const int e0 = et * TP_TILE;
        const int n0 = nt * TP_TILE;

        // Load M tile: 64 rows x 16 float4/row = 1024 float4s.
        #pragma unroll
        for (int j = 0; j < 4; j++) {
            const int idx  = tid + 256 * j;
            const int lrow = idx >> 4;        // n_local 0..63
            const int lc4  = idx & 15;        // e_local/4 0..15
            const float4 m4 = reinterpret_cast<const float4*>(
                M + (long)(n0 + lrow) * EE + e0)[lc4];
            tile[lrow][lc4 * 4 + 0] = m4.x;
            tile[lrow][lc4 * 4 + 1] = m4.y;
            tile[lrow][lc4 * 4 + 2] = m4.z;
            tile[lrow][lc4 * 4 + 3] = m4.w;
        }
        __syncthreads();

        // Store transposed: 64 out-rows x 16 float4/row.
        #pragma unroll
        for (int j = 0; j < 4; j++) {
            const int idx  = tid + 256 * j;
            const int orow = idx >> 4;        // e_local 0..63
            const int oc4  = idx & 15;        // n_local/4 0..15
            const int nl   = oc4 * 4;
            float4 v;
            v.x = -tile[nl + 0][orow];
            v.y = -tile[nl + 1][orow];
            v.z = -tile[nl + 2][orow];
            v.w = -tile[nl + 3][orow];
            __stcs(&reinterpret_cast<float4*>(
                out + (long)(NN + e0 + orow) * WW + 2 * EE + n0)[oc4], v);
        }
    }
}

extern "C" void kernel_launch(void* const* d_in, const int* in_sizes, int n_in,
                              void* d_out, int out_size)
{
    const float* M      = (const float*)d_in[0];
    const float* params = (const float*)d_in[1];
    const int*   kinds  = (const int*)d_in[2];
    float*       out    = (float*)d_out;

    (void)in_sizes; (void)n_in; (void)out_size;

    fused_kernel<<<TOTAL_BLOCKS, 256>>>(M, params, kinds, out);
}

// round 5
// speedup vs baseline: 1.1835x; 1.1835x over previous
#include <cuda_runtime.h>

// Problem constants (fixed by the reference):
//   N_NODES = 2048, N_ELEMS = 4096
//   Output: (N + 2E) x (2E + N) = 10240 x 10240 fp32
#define NN 2048
#define EE 4096
#define WW (2 * EE + NN)   // 10240
#define W4 (WW / 4)        // 2560

// 2D grid: x = 10 column strips (256 float4 each), y = 820 transpose rows
// followed by 10240 fill rows.
#define TP_YROWS 820                     // 820*10 = 8200 >= 8192 tiles
#define TP_TILES_X (EE / 32)             // 128
#define TP_TILES_Y (NN / 32)             // 64
#define NUM_TP_TILES (TP_TILES_X * TP_TILES_Y)   // 8192
#define GRID_Y (TP_YROWS + WW)           // 11060

__global__ void __launch_bounds__(256) fused_kernel(
    const float* __restrict__ M,
    const float* __restrict__ params,
    const int* __restrict__ kinds,
    float* __restrict__ out)
{
    const int tid = threadIdx.x;

    if (blockIdx.y >= TP_YROWS) {
        // ------------------------------------------------------------------
        // FILL path: row = blockIdx.y - TP_YROWS, strip = blockIdx.x.
        // One float4 per thread, plain stores (R1-proven 6.8 TB/s pattern).
        // ------------------------------------------------------------------
        const int row = blockIdx.y - TP_YROWS;
        const int c4  = blockIdx.x * 256 + tid;      // 0 .. 2559
        const int col = c4 * 4;

        float4 v = make_float4(0.f, 0.f, 0.f, 0.f);

        if (row < NN) {
            // kcl rows: [ M | 0 ]
            if (col < EE) {
                v = reinterpret_cast<const float4*>(M)[row * (EE / 4) + c4];
            }
        } else if (row < NN + EE) {
            // kvl rows: [ 0 | I_E | -M^T ]
            if (col >= 2 * EE) return;   // -M^T written by transpose blocks
            const int r = row - NN;
            if (col >= EE) {
                const int d = EE + r;    // column of the identity 1
                if (d >= col && d < col + 4) {
                    reinterpret_cast<float*>(&v)[d - col] = 1.0f;
                }
            }
        } else {
            // elem rows: z diag at col=pos, y diag at col=E+pos
            const int pos = row - NN - EE;
            const int yc  = EE + pos;
            if (pos >= col && pos < col + 4) {
                const float p = params[pos];
                const int   k = kinds[pos];
                float z = 0.0f;
                if (k == 0)                      z = -p;   // R
                else if (k == 2)                 z = 1.0f; // VC
                else if (k == 3 && !(p > 0.0f))  z = 1.0f; // SW off
                reinterpret_cast<float*>(&v)[pos - col] = z;
            }
            if (yc >= col && yc < col + 4) {
                const float p = params[pos];
                const int   k = kinds[pos];
                const float y = (k == 0 || k == 1 || (k == 3 && p > 0.0f)) ? 1.0f : 0.0f;
                reinterpret_cast<float*>(&v)[yc - col] = y;
            }
        }

        reinterpret_cast<float4*>(out)[row * W4 + c4] = v;
    } else {
        // ------------------------------------------------------------------
        // TRANSPOSE path: out[NN + e][2*EE + n] = -M[n][e], 32x32 tiles.
        // Coalesced float4 read of M + float4 write of out via padded smem.
        // ------------------------------------------------------------------
        const int t = blockIdx.y * 10 + blockIdx.x;
        if (t >= NUM_TP_TILES) return;

        __shared__ float tile[32][33];   // [n_local][e_local]

        const int et = t % TP_TILES_X;
        const int nt = t / TP_TILES_X;
        const int e0 = et * 32;
        const int n0 = nt * 32;

        // Load: 256 threads, one float4 each (32 rows x 8 float4/row)
        {
            const int lrow = tid >> 3;          // 0..31  (n_local)
            const int lc4  = tid & 7;           // 0..7   (e_local/4)
            const float4 m4 = reinterpret_cast<const float4*>(
                M + (n0 + lrow) * EE + e0)[lc4];
            tile[lrow][lc4 * 4 + 0] = m4.x;
            tile[lrow][lc4 * 4 + 1] = m4.y;
            tile[lrow][lc4 * 4 + 2] = m4.z;
            tile[lrow][lc4 * 4 + 3] = m4.w;
        }
        __syncthreads();

        // Store: one float4 of output per thread. orow=e_local, oc4=n_local/4
        {
            const int orow = tid >> 3;          // 0..31
            const int oc4  = tid & 7;           // 0..7
            const int nl   = oc4 * 4;
            float4 v;
            v.x = -tile[nl + 0][orow];
            v.y = -tile[nl + 1][orow];
            v.z = -tile[nl + 2][orow];
            v.w = -tile[nl + 3][orow];
            reinterpret_cast<float4*>(
                out + (NN + e0 + orow) * WW + 2 * EE + n0)[oc4] = v;
        }
    }
}

extern "C" void kernel_launch(void* const* d_in, const int* in_sizes, int n_in,
                              void* d_out, int out_size)
{
    const float* M      = (const float*)d_in[0];
    const float* params = (const float*)d_in[1];
    const int*   kinds  = (const int*)d_in[2];
    float*       out    = (float*)d_out;

    (void)in_sizes; (void)n_in; (void)out_size;

    dim3 grid(10, GRID_Y, 1);
    fused_kernel<<<grid, 256>>>(M, params, kinds, out);
}